// round 1
// baseline (speedup 1.0000x reference)
#include <cuda_runtime.h>
#include <cuda_bf16.h>
#include <math.h>

// ---------------- problem constants ----------------
#define D_BATCH 8
#define N_SEQ   2048
#define T_TOK   (D_BATCH * N_SEQ)   // 16384
#define DM      1024
#define FF      4096
#define VOCAB   32000
#define NCAT    75
#define D_HALF  512
#define LN_EPS  1e-5f

// ---------------- scratch (device globals; no allocation allowed) ----------------
__device__ float g_x  [(size_t)T_TOK * DM];
__device__ float g_q  [(size_t)T_TOK * DM];
__device__ float g_k  [(size_t)T_TOK * DM];
__device__ float g_v  [(size_t)T_TOK * DM];
__device__ float g_M  [(size_t)D_BATCH * DM * DM];   // K^T V  per batch
__device__ float g_M2 [(size_t)D_BATCH * DM * DM];   // (K^T V) Wu / 8
__device__ float g_u  [(size_t)T_TOK * DM];
__device__ float g_h1 [(size_t)T_TOK * DM];
__device__ float g_t1 [(size_t)T_TOK * FF];
__device__ float g_ffo[(size_t)T_TOK * DM];
__device__ float g_h2 [(size_t)T_TOK * DM];
__device__ float g_t3 [(size_t)T_TOK * D_HALF];
__device__ float g_lg [(size_t)T_TOK * NCAT];

// ---------------- embed + positional encoding ----------------
__global__ void embed_kernel(const int* __restrict__ idx,
                             const float* __restrict__ emb,
                             float* __restrict__ x)
{
    int row = blockIdx.x;           // token index 0..16383
    int pos = row & (N_SEQ - 1);    // position within sequence
    int t   = threadIdx.x;          // 256 threads, 4 cols each
    int id  = idx[row];
    if (id >= VOCAB || id < 0) id = 1;

    int c0 = t * 4;                 // even
    int p0 = c0 >> 1;               // pair index for cols c0,c0+1
    int p1 = p0 + 1;                // pair index for cols c0+2,c0+3

    double inv0 = pow(10000.0, -(double)p0 / 512.0);
    double inv1 = pow(10000.0, -(double)p1 / 512.0);
    float ang0 = (float)((double)pos * inv0);
    float ang1 = (float)((double)pos * inv1);
    float s0, cO0, s1, cO1;
    sincosf(ang0, &s0, &cO0);
    sincosf(ang1, &s1, &cO1);

    float4 e = *reinterpret_cast<const float4*>(emb + (size_t)id * DM + c0);
    float4 o;
    o.x = e.x + s0;
    o.y = e.y + cO0;
    o.z = e.z + s1;
    o.w = e.w + cO1;
    *reinterpret_cast<float4*>(x + (size_t)row * DM + c0) = o;
}

// ---------------- generic tiled SGEMM ----------------
// C[b] = alpha * op(A[b]) @ B[b] + bias  (optional relu)
// op(A) = A        (TRANSA=false): A is [M,K], lda = row stride
// op(A) = A^T      (TRANSA=true) : A is [K,M], lda = row stride
// B is [K,N] row-major. Batched via grid.z with element strides sA,sB,sC.
#define BM 128
#define BN 128
#define BKK 16
#define TM 8
#define TN 8

template<bool TRANSA, bool RELU>
__global__ __launch_bounds__(256)
void gemm_kernel(const float* __restrict__ A, const float* __restrict__ B,
                 const float* __restrict__ bias, float* __restrict__ C,
                 int M, int N, int K, int lda, int ldb, int ldc,
                 size_t sA, size_t sB, size_t sC, float alpha)
{
    __shared__ float As[BKK][BM];
    __shared__ float Bs[BKK][BN];

    int b = blockIdx.z;
    A += (size_t)b * sA;
    B += (size_t)b * sB;
    C += (size_t)b * sC;

    int m0 = blockIdx.y * BM;
    int n0 = blockIdx.x * BN;
    int tid = threadIdx.x;
    int tx = tid & 15;      // 0..15
    int ty = tid >> 4;      // 0..15

    float acc[TM][TN];
#pragma unroll
    for (int i = 0; i < TM; ++i)
#pragma unroll
        for (int j = 0; j < TN; ++j) acc[i][j] = 0.f;

    const bool nvec = ((N & 3) == 0);

    for (int k0 = 0; k0 < K; k0 += BKK) {
        // ---- load A tile into As[k][m] ----
        if (!TRANSA) {
#pragma unroll
            for (int it = 0; it < 2; ++it) {
                int idx4 = tid + it * 256;      // 0..511
                int row  = idx4 >> 2;           // 0..127  (m within tile)
                int kc   = (idx4 & 3) * 4;      // 0,4,8,12
                float4 av = make_float4(0.f, 0.f, 0.f, 0.f);
                int gm = m0 + row;
                if (gm < M)
                    av = *reinterpret_cast<const float4*>(A + (size_t)gm * lda + k0 + kc);
                As[kc + 0][row] = av.x;
                As[kc + 1][row] = av.y;
                As[kc + 2][row] = av.z;
                As[kc + 3][row] = av.w;
            }
        } else {
#pragma unroll
            for (int it = 0; it < 2; ++it) {
                int idx4 = tid + it * 256;
                int row  = idx4 >> 5;           // 0..15 (k within tile)
                int mc   = (idx4 & 31) * 4;     // 0..124
                const float* ap = A + (size_t)(k0 + row) * lda;
                float4 av;
                int gm = m0 + mc;
                if (gm + 3 < M) {
                    av = *reinterpret_cast<const float4*>(ap + gm);
                } else {
                    av.x = (gm + 0 < M) ? ap[gm + 0] : 0.f;
                    av.y = (gm + 1 < M) ? ap[gm + 1] : 0.f;
                    av.z = (gm + 2 < M) ? ap[gm + 2] : 0.f;
                    av.w = (gm + 3 < M) ? ap[gm + 3] : 0.f;
                }
                *reinterpret_cast<float4*>(&As[row][mc]) = av;
            }
        }
        // ---- load B tile into Bs[k][n] ----
#pragma unroll
        for (int it = 0; it < 2; ++it) {
            int idx4 = tid + it * 256;
            int row  = idx4 >> 5;               // 0..15
            int nc   = (idx4 & 31) * 4;         // 0..124
            float4 bv = make_float4(0.f, 0.f, 0.f, 0.f);
            int gn = n0 + nc;
            const float* bp = B + (size_t)(k0 + row) * ldb;
            if (nvec) {
                if (gn < N) bv = *reinterpret_cast<const float4*>(bp + gn);
            } else {
                if (gn + 0 < N) bv.x = bp[gn + 0];
                if (gn + 1 < N) bv.y = bp[gn + 1];
                if (gn + 2 < N) bv.z = bp[gn + 2];
                if (gn + 3 < N) bv.w = bp[gn + 3];
            }
            *reinterpret_cast<float4*>(&Bs[row][nc]) = bv;
        }
        __syncthreads();

#pragma unroll
        for (int kk = 0; kk < BKK; ++kk) {
            float a[TM], bb[TN];
#pragma unroll
            for (int i = 0; i < TM; ++i) a[i] = As[kk][ty * TM + i];
#pragma unroll
            for (int j = 0; j < TN; ++j) bb[j] = Bs[kk][tx * TN + j];
#pragma unroll
            for (int i = 0; i < TM; ++i)
#pragma unroll
                for (int j = 0; j < TN; ++j)
                    acc[i][j] += a[i] * bb[j];
        }
        __syncthreads();
    }

    // ---- epilogue ----
#pragma unroll
    for (int i = 0; i < TM; ++i) {
        int gm = m0 + ty * TM + i;
        if (gm >= M) continue;
        float* cp = C + (size_t)gm * ldc;
#pragma unroll
        for (int j = 0; j < TN; ++j) {
            int gn = n0 + tx * TN + j;
            if (gn >= N) continue;
            float vv = acc[i][j] * alpha;
            if (bias) vv += bias[gn];
            if (RELU) vv = fmaxf(vv, 0.f);
            cp[gn] = vv;
        }
    }
}

// ---------------- residual + layernorm over 1024 ----------------
__global__ __launch_bounds__(256)
void add_ln_kernel(const float* __restrict__ X, const float* __restrict__ U,
                   const float* __restrict__ g, const float* __restrict__ be,
                   float* __restrict__ out)
{
    __shared__ float ssum[8], ssq[8];
    __shared__ float smu, srs;
    int row = blockIdx.x;
    int t = threadIdx.x;

    float4 xv = *reinterpret_cast<const float4*>(X + (size_t)row * DM + t * 4);
    float4 uv = *reinterpret_cast<const float4*>(U + (size_t)row * DM + t * 4);
    float v0 = xv.x + uv.x, v1 = xv.y + uv.y, v2 = xv.z + uv.z, v3 = xv.w + uv.w;

    float s  = v0 + v1 + v2 + v3;
    float q  = v0 * v0 + v1 * v1 + v2 * v2 + v3 * v3;
#pragma unroll
    for (int o = 16; o; o >>= 1) {
        s += __shfl_xor_sync(0xFFFFFFFFu, s, o);
        q += __shfl_xor_sync(0xFFFFFFFFu, q, o);
    }
    int warp = t >> 5, lane = t & 31;
    if (lane == 0) { ssum[warp] = s; ssq[warp] = q; }
    __syncthreads();
    if (t == 0) {
        float S = 0.f, Q = 0.f;
#pragma unroll
        for (int i = 0; i < 8; ++i) { S += ssum[i]; Q += ssq[i]; }
        float mu = S * (1.f / DM);
        float var = Q * (1.f / DM) - mu * mu;
        smu = mu;
        srs = rsqrtf(var + LN_EPS);
    }
    __syncthreads();
    float mu = smu, rs = srs;

    float4 gv  = *reinterpret_cast<const float4*>(g  + t * 4);
    float4 bv  = *reinterpret_cast<const float4*>(be + t * 4);
    float4 o;
    o.x = (v0 - mu) * rs * gv.x + bv.x;
    o.y = (v1 - mu) * rs * gv.y + bv.y;
    o.z = (v2 - mu) * rs * gv.z + bv.z;
    o.w = (v3 - mu) * rs * gv.w + bv.w;
    *reinterpret_cast<float4*>(out + (size_t)row * DM + t * 4) = o;
}

// ---------------- final: sigmoid(layernorm(logits)) over 75 ----------------
__global__ __launch_bounds__(256)
void final_kernel(const float* __restrict__ lg,
                  const float* __restrict__ g, const float* __restrict__ be,
                  float* __restrict__ out)
{
    int row = blockIdx.x * 8 + (threadIdx.x >> 5);
    int lane = threadIdx.x & 31;
    if (row >= T_TOK) return;
    const float* lp = lg + (size_t)row * NCAT;

    float v[3];
    float s = 0.f, q = 0.f;
#pragma unroll
    for (int i = 0; i < 3; ++i) {
        int c = lane + i * 32;
        float x = (c < NCAT) ? lp[c] : 0.f;
        v[i] = x;
        s += x;
        q += x * x;
    }
#pragma unroll
    for (int o = 16; o; o >>= 1) {
        s += __shfl_xor_sync(0xFFFFFFFFu, s, o);
        q += __shfl_xor_sync(0xFFFFFFFFu, q, o);
    }
    float mu  = s * (1.f / NCAT);
    float var = q * (1.f / NCAT) - mu * mu;
    float rs  = rsqrtf(var + LN_EPS);

    float* op = out + (size_t)row * NCAT;
#pragma unroll
    for (int i = 0; i < 3; ++i) {
        int c = lane + i * 32;
        if (c < NCAT) {
            float z = (v[i] - mu) * rs * g[c] + be[c];
            op[c] = 1.f / (1.f + expf(-z));
        }
    }
}

// ---------------- host launcher ----------------
extern "C" void kernel_launch(void* const* d_in, const int* in_sizes, int n_in,
                              void* d_out, int out_size)
{
    const int*   idx = (const int*)  d_in[0];
    const float* emb = (const float*)d_in[1];
    const float* Wq  = (const float*)d_in[2];
    const float* bq  = (const float*)d_in[3];
    const float* Wk  = (const float*)d_in[4];
    const float* bk  = (const float*)d_in[5];
    const float* Wv  = (const float*)d_in[6];
    const float* bv  = (const float*)d_in[7];
    const float* Wu  = (const float*)d_in[8];
    const float* bu  = (const float*)d_in[9];
    const float* g1  = (const float*)d_in[10];
    const float* be1 = (const float*)d_in[11];
    const float* W1  = (const float*)d_in[12];
    const float* b1  = (const float*)d_in[13];
    const float* W2  = (const float*)d_in[14];
    const float* b2  = (const float*)d_in[15];
    const float* g2  = (const float*)d_in[16];
    const float* be2 = (const float*)d_in[17];
    const float* W3  = (const float*)d_in[18];
    const float* b3  = (const float*)d_in[19];
    const float* W4  = (const float*)d_in[20];
    const float* b4  = (const float*)d_in[21];
    const float* g3  = (const float*)d_in[22];
    const float* be3 = (const float*)d_in[23];
    float* out = (float*)d_out;

    float *x, *q, *k, *v, *Mb, *M2, *u, *h1, *t1, *ffo, *h2, *t3, *lg;
    cudaGetSymbolAddress((void**)&x,  g_x);
    cudaGetSymbolAddress((void**)&q,  g_q);
    cudaGetSymbolAddress((void**)&k,  g_k);
    cudaGetSymbolAddress((void**)&v,  g_v);
    cudaGetSymbolAddress((void**)&Mb, g_M);
    cudaGetSymbolAddress((void**)&M2, g_M2);
    cudaGetSymbolAddress((void**)&u,  g_u);
    cudaGetSymbolAddress((void**)&h1, g_h1);
    cudaGetSymbolAddress((void**)&t1, g_t1);
    cudaGetSymbolAddress((void**)&ffo,g_ffo);
    cudaGetSymbolAddress((void**)&h2, g_h2);
    cudaGetSymbolAddress((void**)&t3, g_t3);
    cudaGetSymbolAddress((void**)&lg, g_lg);

    // 1. x = emb[idx] + posenc
    embed_kernel<<<T_TOK, 256>>>(idx, emb, x);

    // 2-4. Q/K/V projections: [16384,1024] @ [1024,1024]
    dim3 gQKV(DM / BN, T_TOK / BM, 1);
    gemm_kernel<false,false><<<gQKV, 256>>>(x, Wq, bq, q, T_TOK, DM, DM, DM, DM, DM, 0, 0, 0, 1.f);
    gemm_kernel<false,false><<<gQKV, 256>>>(x, Wk, bk, k, T_TOK, DM, DM, DM, DM, DM, 0, 0, 0, 1.f);
    gemm_kernel<false,false><<<gQKV, 256>>>(x, Wv, bv, v, T_TOK, DM, DM, DM, DM, DM, 0, 0, 0, 1.f);

    // 5. Mb = K^T V per batch  (softmax-free attention reassociation)
    dim3 gKTV(DM / BN, DM / BM, D_BATCH);
    gemm_kernel<true,false><<<gKTV, 256>>>(k, v, nullptr, Mb, DM, DM, N_SEQ,
                                           DM, DM, DM,
                                           (size_t)N_SEQ * DM, (size_t)N_SEQ * DM,
                                           (size_t)DM * DM, 1.f);

    // 6. M2 = (Mb @ Wu) / 8  (1/sqrt(dk) folded in)
    dim3 gM2(DM / BN, DM / BM, D_BATCH);
    gemm_kernel<false,false><<<gM2, 256>>>(Mb, Wu, nullptr, M2, DM, DM, DM,
                                           DM, DM, DM,
                                           (size_t)DM * DM, 0, (size_t)DM * DM, 0.125f);

    // 7. u = Q @ M2 + bu per batch
    dim3 gU(DM / BN, N_SEQ / BM, D_BATCH);
    gemm_kernel<false,false><<<gU, 256>>>(q, M2, bu, u, N_SEQ, DM, DM,
                                          DM, DM, DM,
                                          (size_t)N_SEQ * DM, (size_t)DM * DM,
                                          (size_t)N_SEQ * DM, 1.f);

    // 8. h1 = LN(x + u)
    add_ln_kernel<<<T_TOK, 256>>>(x, u, g1, be1, h1);

    // 9. t1 = relu(h1 @ W1 + b1)   [16384,4096]
    dim3 gF1(FF / BN, T_TOK / BM, 1);
    gemm_kernel<false,true><<<gF1, 256>>>(h1, W1, b1, t1, T_TOK, FF, DM, DM, FF, FF, 0, 0, 0, 1.f);

    // 10. ffo = t1 @ W2 + b2
    dim3 gF2(DM / BN, T_TOK / BM, 1);
    gemm_kernel<false,false><<<gF2, 256>>>(t1, W2, b2, ffo, T_TOK, DM, FF, FF, DM, DM, 0, 0, 0, 1.f);

    // 11. h2 = LN(h1 + ffo)
    add_ln_kernel<<<T_TOK, 256>>>(h1, ffo, g2, be2, h2);

    // 12. t3 = relu(h2 @ W3 + b3)  [16384,512]
    dim3 gH(D_HALF / BN, T_TOK / BM, 1);
    gemm_kernel<false,true><<<gH, 256>>>(h2, W3, b3, t3, T_TOK, D_HALF, DM, DM, D_HALF, D_HALF, 0, 0, 0, 1.f);

    // 13. logits = t3 @ W4 + b4    [16384,75]
    dim3 gL((NCAT + BN - 1) / BN, T_TOK / BM, 1);
    gemm_kernel<false,false><<<gL, 256>>>(t3, W4, b4, lg, T_TOK, NCAT, D_HALF,
                                          D_HALF, NCAT, NCAT, 0, 0, 0, 1.f);

    // 14. out = sigmoid(LN(logits))
    final_kernel<<<T_TOK / 8, 256>>>(lg, g3, be3, out);
}